// round 14
// baseline (speedup 1.0000x reference)
#include <cuda_runtime.h>
#include <cuda_bf16.h>

#define THREADS 256
#define ROWS_PER_CHUNK (THREADS * 2)
#define GMAX 4096
#define SMS 148
#define OCC 8

// {count, sum_col11, sum_col24, pad} per graph; zero-initialized at module load.
// mlp_reset_kernel re-zeroes after consuming, so every replay starts from zeros.
__device__ float4 g_acc[GMAX];

// Persistent-CTA segmented sum over sorted batch ids. One full resident wave
// (148*8 blocks); each block grid-strides over 512-row chunks. Two consecutive
// rows per thread per chunk: int2 batch load + 4 feature loads, pair combined
// locally (same graph) with a rare direct-atomic path for split pairs.
__global__ void __launch_bounds__(THREADS)
seg_reduce_kernel(const float* __restrict__ nf,
                  const int* __restrict__ batch,
                  int N) {
    const int lane = threadIdx.x & 31;
    const int stride = gridDim.x * ROWS_PER_CHUNK;

    for (int base = blockIdx.x * ROWS_PER_CHUNK; base < N; base += stride) {
        const int r = base + 2 * threadIdx.x;

        int   g0 = -1, g1 = -1;
        float f0x = 0.f, f0y = 0.f, f1x = 0.f, f1y = 0.f;

        if (r + 1 < N) {
            int2 bb = __ldcs((const int2*)(batch + r));   // rows r, r+1
            g0 = bb.x; g1 = bb.y;
            const float* row0 = nf + (size_t)r * 128;
            f0x = __ldcs(row0 + 11);          // MODIFIER_COL
            f0y = __ldcs(row0 + 24);          // OWNER_COL
            f1x = __ldcs(row0 + 128 + 11);
            f1y = __ldcs(row0 + 128 + 24);
        } else if (r < N) {                   // tail odd row
            g0 = __ldcs(batch + r);
            const float* row0 = nf + (size_t)r * 128;
            f0x = __ldcs(row0 + 11);
            f0y = __ldcs(row0 + 24);
        }

        // Combine the pair when same graph; else second row via rare path.
        bool same = (g0 == g1);
        float c  = (g0 >= 0) ? (same ? 2.0f : 1.0f) : 0.0f;
        float v0 = f0x + (same ? f1x : 0.0f);
        float v1 = f0y + (same ? f1y : 0.0f);

        if (g1 >= 0 && !same) {               // ~1 per graph boundary at odd offset
            float* bp = (float*)&g_acc[g1];
            atomicAdd(bp + 0, 1.0f);
            atomicAdd(bp + 1, f1x);
            atomicAdd(bp + 2, f1y);
        }

        // Segmented warp reduce over g0 (nondecreasing across lanes).
        unsigned peers  = __match_any_sync(0xffffffffu, g0);
        int      leader = __ffs(peers) - 1;
        int      cnt    = __popc(peers);
        #pragma unroll
        for (int off = 16; off > 0; off >>= 1) {
            float t0 = __shfl_down_sync(0xffffffffu, v0, off);
            float t1 = __shfl_down_sync(0xffffffffu, v1, off);
            float tc = __shfl_down_sync(0xffffffffu, c,  off);
            if (lane + off < leader + cnt) { v0 += t0; v1 += t1; c += tc; }
        }
        if (lane == leader && g0 >= 0) {
            float* bp = (float*)&g_acc[g0];
            atomicAdd(bp + 0, c);
            atomicAdd(bp + 1, v0);
            atomicAdd(bp + 2, v1);
        }
    }

#if __CUDA_ARCH__ >= 900
    // All block atomics issued; release to the dependent grid before teardown.
    __syncthreads();
    cudaTriggerProgrammaticLaunchCompletion();
#endif
}

// Consume accumulators, run tiny MLP, write out, RESET accumulators for the
// next replay. PDL: launches during seg_reduce; weights load before the
// dependency sync so only the g_acc read chain is exposed.
__global__ void mlp_reset_kernel(const float* __restrict__ W1,   // [32,2]
                                 const float* __restrict__ b1,   // [32]
                                 const float* __restrict__ W2,   // [1,32]
                                 const float* __restrict__ b2,   // [1]
                                 float* __restrict__ out, int G) {
    int g = blockIdx.x * blockDim.x + threadIdx.x;

    // Independent prologue: pull weights while the primary kernel drains.
    float w1a[32], w1b[32], w2[32];
    float bb1[32], bias2 = __ldg(b2);
    #pragma unroll
    for (int j = 0; j < 32; j++) {
        w1a[j] = __ldg(W1 + j * 2 + 0);
        w1b[j] = __ldg(W1 + j * 2 + 1);
        bb1[j] = __ldg(b1 + j);
        w2[j]  = __ldg(W2 + j);
    }

#if __CUDA_ARCH__ >= 900
    cudaGridDependencySynchronize();
#endif

    if (g >= G) return;

    float4 a = g_acc[g];                         // one LDG.128
    g_acc[g] = make_float4(0.f, 0.f, 0.f, 0.f);  // one STG.128 reset

    float denom = fmaxf(a.x, 1.0f);
    float a0 = 1.0f - a.y / denom;
    float a1 = 1.0f - a.z / denom;

    float acc = bias2;
    #pragma unroll
    for (int j = 0; j < 32; j++) {
        float h = fmaf(a0, w1a[j], fmaf(a1, w1b[j], bb1[j]));
        h = fmaxf(h, 0.0f);
        acc = fmaf(h, w2[j], acc);
    }
    float score = 1.0f / (1.0f + __expf(-acc));
    out[g] = (a.x > 0.0f) ? score : 0.0f;
}

extern "C" void kernel_launch(void* const* d_in, const int* in_sizes, int n_in,
                              void* d_out, int out_size) {
    // metadata order: node_features, batch, graph_embedding(unused), W1, b1, W2, b2
    const float* nf    = (const float*)d_in[0];
    const int*   batch = (const int*)d_in[1];
    const float* W1    = (const float*)d_in[3];
    const float* b1    = (const float*)d_in[4];
    const float* W2    = (const float*)d_in[5];
    const float* b2    = (const float*)d_in[6];
    float*       out   = (float*)d_out;

    int N = in_sizes[1];   // number of nodes
    int G = out_size;      // number of graphs
    if (G > GMAX) G = GMAX;

    int nchunks = (N + ROWS_PER_CHUNK - 1) / ROWS_PER_CHUNK;
    int nblocks = SMS * OCC;                 // one full resident wave
    if (nblocks > nchunks) nblocks = nchunks;
    seg_reduce_kernel<<<nblocks, THREADS>>>(nf, batch, N);

    // PDL launch of the epilogue: overlaps its launch + weight loads with seg_reduce.
    cudaLaunchConfig_t cfg = {};
    cfg.gridDim  = dim3((G + THREADS - 1) / THREADS);
    cfg.blockDim = dim3(THREADS);
    cudaLaunchAttribute attr[1];
    attr[0].id = cudaLaunchAttributeProgrammaticStreamSerialization;
    attr[0].val.programmaticStreamSerializationAllowed = 1;
    cfg.attrs = attr;
    cfg.numAttrs = 1;
    cudaLaunchKernelEx(&cfg, mlp_reset_kernel, W1, b1, W2, b2, out, G);
}

// round 16
// speedup vs baseline: 1.0115x; 1.0115x over previous
#include <cuda_runtime.h>
#include <cuda_bf16.h>

#define THREADS 256
#define ROWS_PER_BLOCK (THREADS * 2)
#define GMAX 4096

// {count, sum_col11, sum_col24, pad} per graph; zero-initialized at module load.
// mlp_reset_kernel re-zeroes after consuming, so every replay starts from zeros.
__device__ float4 g_acc[GMAX];

// Segmented sum over sorted batch ids. TWO CONSECUTIVE rows per thread:
// one int2 batch load + 4 feature loads (streaming). Pair combined locally
// when both rows share a graph (overwhelmingly common); split pairs send the
// second row via a rare direct-atomic path. One match/shuffle chain per pair.
__global__ void __launch_bounds__(THREADS)
seg_reduce_kernel(const float* __restrict__ nf,
                  const int* __restrict__ batch,
                  int N) {
    const int lane = threadIdx.x & 31;
    const int r = blockIdx.x * ROWS_PER_BLOCK + 2 * threadIdx.x;

    int   g0 = -1, g1 = -1;
    float f0x = 0.f, f0y = 0.f, f1x = 0.f, f1y = 0.f;

    if (r + 1 < N) {
        int2 bb = __ldcs((const int2*)(batch + r));   // rows r, r+1 (8B aligned)
        g0 = bb.x; g1 = bb.y;
        const float* row0 = nf + (size_t)r * 128;
        f0x = __ldcs(row0 + 11);          // MODIFIER_COL
        f0y = __ldcs(row0 + 24);          // OWNER_COL
        f1x = __ldcs(row0 + 128 + 11);
        f1y = __ldcs(row0 + 128 + 24);
    } else if (r < N) {                   // tail odd row
        g0 = __ldcs(batch + r);
        const float* row0 = nf + (size_t)r * 128;
        f0x = __ldcs(row0 + 11);
        f0y = __ldcs(row0 + 24);
    }

    // Combine the pair when same graph; else second row goes via rare path.
    bool same = (g0 == g1);
    float c  = (g0 >= 0) ? (same ? 2.0f : 1.0f) : 0.0f;
    float v0 = f0x + (same ? f1x : 0.0f);
    float v1 = f0y + (same ? f1y : 0.0f);

    if (g1 >= 0 && !same) {               // ~1 per graph boundary at odd offset
        float* bp = (float*)&g_acc[g1];
        atomicAdd(bp + 0, 1.0f);
        atomicAdd(bp + 1, f1x);
        atomicAdd(bp + 2, f1y);
    }

    // Segmented warp reduce over g0 (nondecreasing across lanes -> contiguous runs).
    unsigned peers  = __match_any_sync(0xffffffffu, g0);
    int      leader = __ffs(peers) - 1;
    int      cnt    = __popc(peers);
    #pragma unroll
    for (int off = 16; off > 0; off >>= 1) {
        float t0 = __shfl_down_sync(0xffffffffu, v0, off);
        float t1 = __shfl_down_sync(0xffffffffu, v1, off);
        float tc = __shfl_down_sync(0xffffffffu, c,  off);
        if (lane + off < leader + cnt) { v0 += t0; v1 += t1; c += tc; }
    }
    if (lane == leader && g0 >= 0) {
        float* bp = (float*)&g_acc[g0];
        atomicAdd(bp + 0, c);
        atomicAdd(bp + 1, v0);
        atomicAdd(bp + 2, v1);
    }

#if __CUDA_ARCH__ >= 900
    // All block atomics issued; release to the dependent grid before teardown.
    __syncthreads();
    cudaTriggerProgrammaticLaunchCompletion();
#endif
}

// Consume accumulators, run tiny MLP, write out, RESET accumulators for the
// next replay. PDL: launches during seg_reduce; weights load before the
// dependency sync so only the g_acc read chain is exposed.
__global__ void mlp_reset_kernel(const float* __restrict__ W1,   // [32,2]
                                 const float* __restrict__ b1,   // [32]
                                 const float* __restrict__ W2,   // [1,32]
                                 const float* __restrict__ b2,   // [1]
                                 float* __restrict__ out, int G) {
    int g = blockIdx.x * blockDim.x + threadIdx.x;

    // Independent prologue: pull weights while the primary kernel drains.
    float w1a[32], w1b[32], w2[32];
    float bb1[32], bias2 = __ldg(b2);
    #pragma unroll
    for (int j = 0; j < 32; j++) {
        w1a[j] = __ldg(W1 + j * 2 + 0);
        w1b[j] = __ldg(W1 + j * 2 + 1);
        bb1[j] = __ldg(b1 + j);
        w2[j]  = __ldg(W2 + j);
    }

#if __CUDA_ARCH__ >= 900
    cudaGridDependencySynchronize();
#endif

    if (g >= G) return;

    float4 a = g_acc[g];                         // one LDG.128 (L2-resident)
    g_acc[g] = make_float4(0.f, 0.f, 0.f, 0.f);  // one STG.128 reset

    float denom = fmaxf(a.x, 1.0f);
    float a0 = 1.0f - a.y / denom;
    float a1 = 1.0f - a.z / denom;

    float acc = bias2;
    #pragma unroll
    for (int j = 0; j < 32; j++) {
        float h = fmaf(a0, w1a[j], fmaf(a1, w1b[j], bb1[j]));
        h = fmaxf(h, 0.0f);
        acc = fmaf(h, w2[j], acc);
    }
    float score = 1.0f / (1.0f + __expf(-acc));
    out[g] = (a.x > 0.0f) ? score : 0.0f;
}

extern "C" void kernel_launch(void* const* d_in, const int* in_sizes, int n_in,
                              void* d_out, int out_size) {
    // metadata order: node_features, batch, graph_embedding(unused), W1, b1, W2, b2
    const float* nf    = (const float*)d_in[0];
    const int*   batch = (const int*)d_in[1];
    const float* W1    = (const float*)d_in[3];
    const float* b1    = (const float*)d_in[4];
    const float* W2    = (const float*)d_in[5];
    const float* b2    = (const float*)d_in[6];
    float*       out   = (float*)d_out;

    int N = in_sizes[1];   // number of nodes
    int G = out_size;      // number of graphs
    if (G > GMAX) G = GMAX;

    int nblocks = (N + ROWS_PER_BLOCK - 1) / ROWS_PER_BLOCK;
    seg_reduce_kernel<<<nblocks, THREADS>>>(nf, batch, N);

    // PDL launch of the epilogue: overlaps its launch + weight loads with
    // seg_reduce. 16 x 128 spreads the latency-bound tail over more SMs.
    cudaLaunchConfig_t cfg = {};
    cfg.gridDim  = dim3((G + 127) / 128);
    cfg.blockDim = dim3(128);
    cudaLaunchAttribute attr[1];
    attr[0].id = cudaLaunchAttributeProgrammaticStreamSerialization;
    attr[0].val.programmaticStreamSerializationAllowed = 1;
    cfg.attrs = attr;
    cfg.numAttrs = 1;
    cudaLaunchKernelEx(&cfg, mlp_reset_kernel, W1, b1, W2, b2, out, G);
}